// round 13
// baseline (speedup 1.0000x reference)
#include <cuda_runtime.h>

#define L_SAMPLES 360000
#define N_BATCH   32
#define T_FRAMES  750
#define KSIZE     1003
#define NCHUNK    22500

#define L1N 1407
#define L1P 1408
#define L2N 88
#define L2P 96
#define L3N 6

#define RCP_SR   (1.0f / 24000.0f)
#define RCP_FS   (1.0f / 480.0f)

__device__ float g_E4[N_BATCH][NCHUNK];
__device__ float g_P [N_BATCH][NCHUNK];
__device__ float g_imp[N_BATCH][L_SAMPLES];

// ---------------------------------------------------------------------------
// Bitwise reference elementwise math (FROZEN — verified)
// ---------------------------------------------------------------------------
__device__ __forceinline__ float f0_interp(const float* __restrict__ f0row, int i) {
    float x = __fmul_rn(__fadd_rn((float)i, 0.5f), RCP_FS);
    x = __fadd_rn(x, -0.5f);
    x = fminf(fmaxf(x, 0.0f), 749.0f);
    float fi0 = floorf(x);
    int i0 = (int)fi0;
    int i1 = i0 + 1; if (i1 > 749) i1 = 749;
    float w = __fadd_rn(x, -fi0);
    float a = __fmul_rn(f0row[i0], __fadd_rn(1.0f, -w));
    float b = __fmul_rn(f0row[i1], w);
    return __fadd_rn(a, b);
}

__device__ __forceinline__ float vval(const float* __restrict__ f0row, int i) {
    return __fmul_rn(-f0_interp(f0row, i), RCP_SR);
}

__device__ __forceinline__ float jmod1(float r) {
    float t = fmodf(r, 1.0f);
    if (t != 0.0f && t < 0.0f) t = __fadd_rn(t, 1.0f);
    return t;
}

__device__ __forceinline__ void seq16(const float* __restrict__ in, float* __restrict__ out) {
    float acc = 0.0f;
#pragma unroll
    for (int i = 0; i < 16; i++) { acc = __fadd_rn(acc, in[i]); out[i] = acc; }
}

// ---------------------------------------------------------------------------
// K1 (FROZEN)
// ---------------------------------------------------------------------------
__global__ void k1_up(const float* __restrict__ f0) {
    __shared__ float sf0[T_FRAMES];
    int row = blockIdx.y;
    for (int j = threadIdx.x; j < T_FRAMES; j += blockDim.x)
        sf0[j] = f0[row * T_FRAMES + j];
    __syncthreads();

    int c = blockIdx.x * blockDim.x + threadIdx.x;
    if (c >= NCHUNK) return;
    int base = c * 16;

    float acc = 0.0f;
#pragma unroll
    for (int j = 0; j < 16; j++) acc = __fadd_rn(acc, vval(sf0, base + j));
    g_E4[row][c] = acc;
}

// ---------------------------------------------------------------------------
// K2 (FROZEN)
// ---------------------------------------------------------------------------
__global__ void k2_mid() {
    extern __shared__ float sm[];
    float* s0 = sm;
    float* s1 = sm + 22512;
    float* s2 = s1 + L1P;
    float* s3 = s2 + L2P;
    int row = blockIdx.x;

    for (int i = threadIdx.x; i < 22512; i += blockDim.x)
        s0[i] = (i < NCHUNK) ? g_E4[row][i] : 0.0f;
    __syncthreads();

    for (int b = threadIdx.x; b < L1N; b += blockDim.x) {
        float w[16];
        seq16(s0 + 16*b, w);
#pragma unroll
        for (int i = 0; i < 16; i++) s0[16*b + i] = w[i];
        s1[b] = w[15];
    }
    if (threadIdx.x == 0) s1[L1N] = 0.0f;
    __syncthreads();

    for (int b = threadIdx.x; b < L2N; b += blockDim.x) {
        float w[16];
        seq16(s1 + 16*b, w);
#pragma unroll
        for (int i = 0; i < 16; i++) s1[16*b + i] = w[i];
        s2[b] = w[15];
    }
    for (int i = L2N + threadIdx.x; i < L2P; i += blockDim.x) s2[i] = 0.0f;
    __syncthreads();

    for (int b = threadIdx.x; b < L3N; b += blockDim.x) {
        float w[16];
        seq16(s2 + 16*b, w);
#pragma unroll
        for (int i = 0; i < 16; i++) s2[16*b + i] = w[i];
        s3[b] = w[15];
    }
    __syncthreads();

    if (threadIdx.x == 0) {
        float acc = 0.0f;
        for (int i = 0; i < L3N; i++) { acc = __fadd_rn(acc, s3[i]); s3[i] = acc; }
    }
    __syncthreads();

    for (int j = threadIdx.x; j < L2N; j += blockDim.x) {
        int b = j >> 4;
        s2[j] = __fadd_rn(s2[j], b ? s3[b-1] : 0.0f);
    }
    __syncthreads();
    for (int j = threadIdx.x; j < L1N; j += blockDim.x) {
        int b = j >> 4;
        s1[j] = __fadd_rn(s1[j], b ? s2[b-1] : 0.0f);
    }
    __syncthreads();
    for (int j = threadIdx.x; j < NCHUNK; j += blockDim.x) {
        int b = j >> 4;
        g_P[row][j] = __fadd_rn(s0[j], b ? s1[b-1] : 0.0f);
    }
}

// ---------------------------------------------------------------------------
// K3 (FROZEN)
// ---------------------------------------------------------------------------
__global__ void k3_impulse(const float* __restrict__ f0) {
    __shared__ float sf0[T_FRAMES];
    int row = blockIdx.y;
    for (int j = threadIdx.x; j < T_FRAMES; j += blockDim.x)
        sf0[j] = f0[row * T_FRAMES + j];
    __syncthreads();

    int c = blockIdx.x * blockDim.x + threadIdx.x;
    if (c >= NCHUNK) return;
    int base = c * 16;

    float e0[16];
#pragma unroll
    for (int j = 0; j < 16; j++) e0[j] = vval(sf0, base + j);
    float h[16];
    seq16(e0, h);

    float P = (c == 0) ? 0.0f : g_P[row][c - 1];

    float pr;
    if (c == 0)      pr = __fadd_rn(g_E4[row][NCHUNK-1], g_P[row][NCHUNK-2]);
    else if (c == 1) pr = __fadd_rn(g_E4[row][0], 0.0f);
    else             pr = __fadd_rn(g_E4[row][c-1], g_P[row][c-2]);
    float prev_saw = jmod1(pr);

#pragma unroll
    for (int j = 0; j < 16; j++) {
        float s = jmod1(__fadd_rn(h[j], P));
        g_imp[row][base + j] = __fadd_rn(s, -prev_saw);
        prev_saw = s;
    }
}

// ---------------------------------------------------------------------------
// K4: 1003-tap FIR with packed f32x2 FMA (FFMA2).
// Window stored twice in smem (normal + shifted-by-1-float), each parity-
// deinterleaved into float4 planes, read as ulonglong2 so all multiplicand
// pairs arrive pre-packed and register-pair-aligned. Weights pre-duplicated
// (w,w). Per-output tap order unchanged -> conv bitwise identical to R11.
// ---------------------------------------------------------------------------
#define CTH    256
#define UO     8
#define OTILE  2048
#define NPLANE 384               // ulonglong2 entries per plane
#define NWQ    504               // 1008 dup-weight pairs as ulonglong2

#define FFMA2(acc, a, b) asm("fma.rn.f32x2 %0, %1, %2, %0;" : "+l"(acc) : "l"(a), "l"(b))

__global__ __launch_bounds__(CTH) void k4_conv(const float* __restrict__ f0,
                                               const float* __restrict__ noise,
                                               const float* __restrict__ kern,
                                               float* __restrict__ out) {
    __shared__ ulonglong2 pl0q [NPLANE];   // normal plane, even float4s
    __shared__ ulonglong2 pl1q [NPLANE];   // normal plane, odd float4s
    __shared__ ulonglong2 pl0sq[NPLANE];   // shifted(+1 float) plane, even
    __shared__ ulonglong2 pl1sq[NPLANE];   // shifted plane, odd
    __shared__ ulonglong2 wq   [NWQ];      // duplicated weights (w,w)
    __shared__ float      sf0  [T_FRAMES];

    const int row  = blockIdx.y;
    const int base = blockIdx.x * OTILE;
    const int t    = threadIdx.x;

    // weights: wf[2k] = wf[2k+1] = kern[k], for ALL 1008 padded taps
    {
        float* wf = (float*)wq;
        for (int k = t; k < 1008; k += CTH) {
            float w = (k < KSIZE) ? kern[k] : 0.0f;
            wf[2*k]   = w;
            wf[2*k+1] = w;
        }
    }
    for (int j = t; j < T_FRAMES; j += CTH)
        sf0[j] = f0[row * T_FRAMES + j];

    // window planes
    {
        const float* impRow = g_imp[row];
        float4* p0 = (float4*)pl0q;
        float4* p1 = (float4*)pl1q;
        float4* s0 = (float4*)pl0sq;
        float4* s1 = (float4*)pl1sq;
        for (int m = t; m < NPLANE; m += CTH) {
            int g = base + 8 * m;
            float4 v0, v1; float nxt;
            if (g + 8 < L_SAMPLES) {
                v0 = *reinterpret_cast<const float4*>(impRow + g);
                v1 = *reinterpret_cast<const float4*>(impRow + g + 4);
                nxt = impRow[g + 8];
            } else {
                float f8[9];
#pragma unroll
                for (int q = 0; q < 9; q++)
                    f8[q] = (g + q < L_SAMPLES) ? impRow[g + q] : 0.0f;
                v0 = make_float4(f8[0], f8[1], f8[2], f8[3]);
                v1 = make_float4(f8[4], f8[5], f8[6], f8[7]);
                nxt = f8[8];
            }
            p0[m] = v0;
            p1[m] = v1;
            s0[m] = make_float4(v0.y, v0.z, v0.w, v1.x);
            s1[m] = make_float4(v1.y, v1.z, v1.w, nxt);
        }
    }
    __syncthreads();

    unsigned long long a0 = 0ull, a1 = 0ull, a2 = 0ull, a3 = 0ull;

    ulonglong2 nA = pl0q[t],  nB = pl1q[t];
    ulonglong2 sA = pl0sq[t], sB = pl1sq[t];

#pragma unroll 2
    for (int it = 0; it < 126; ++it) {
        ulonglong2 nC = pl0q [t + it + 1];
        ulonglong2 nD = pl1q [t + it + 1];
        ulonglong2 sC = pl0sq[t + it + 1];
        ulonglong2 sD = pl1sq[t + it + 1];
        ulonglong2 w01 = wq[4*it + 0];
        ulonglong2 w23 = wq[4*it + 1];
        ulonglong2 w45 = wq[4*it + 2];
        ulonglong2 w67 = wq[4*it + 3];

        // tap 8it+0 : pairs starting at f0,f2,f4,f6
        FFMA2(a0, nA.x, w01.x); FFMA2(a1, nA.y, w01.x);
        FFMA2(a2, nB.x, w01.x); FFMA2(a3, nB.y, w01.x);
        // tap 8it+1 : f1,f3,f5,f7
        FFMA2(a0, sA.x, w01.y); FFMA2(a1, sA.y, w01.y);
        FFMA2(a2, sB.x, w01.y); FFMA2(a3, sB.y, w01.y);
        // tap 8it+2 : f2,f4,f6,f8
        FFMA2(a0, nA.y, w23.x); FFMA2(a1, nB.x, w23.x);
        FFMA2(a2, nB.y, w23.x); FFMA2(a3, nC.x, w23.x);
        // tap 8it+3 : f3,f5,f7,f9
        FFMA2(a0, sA.y, w23.y); FFMA2(a1, sB.x, w23.y);
        FFMA2(a2, sB.y, w23.y); FFMA2(a3, sC.x, w23.y);
        // tap 8it+4 : f4,f6,f8,f10
        FFMA2(a0, nB.x, w45.x); FFMA2(a1, nB.y, w45.x);
        FFMA2(a2, nC.x, w45.x); FFMA2(a3, nC.y, w45.x);
        // tap 8it+5 : f5,f7,f9,f11
        FFMA2(a0, sB.x, w45.y); FFMA2(a1, sB.y, w45.y);
        FFMA2(a2, sC.x, w45.y); FFMA2(a3, sC.y, w45.y);
        // tap 8it+6 : f6,f8,f10,f12
        FFMA2(a0, nB.y, w67.x); FFMA2(a1, nC.x, w67.x);
        FFMA2(a2, nC.y, w67.x); FFMA2(a3, nD.x, w67.x);
        // tap 8it+7 : f7,f9,f11,f13
        FFMA2(a0, sB.y, w67.y); FFMA2(a1, sC.x, w67.y);
        FFMA2(a2, sC.y, w67.y); FFMA2(a3, sD.x, w67.y);

        nA = nC; nB = nD; sA = sC; sB = sD;
    }

    // unpack + epilogue
    float acc[UO];
    asm("mov.b64 {%0,%1}, %2;" : "=f"(acc[0]), "=f"(acc[1]) : "l"(a0));
    asm("mov.b64 {%0,%1}, %2;" : "=f"(acc[2]), "=f"(acc[3]) : "l"(a1));
    asm("mov.b64 {%0,%1}, %2;" : "=f"(acc[4]), "=f"(acc[5]) : "l"(a2));
    asm("mov.b64 {%0,%1}, %2;" : "=f"(acc[6]), "=f"(acc[7]) : "l"(a3));

    int g0 = base + UO * t;
#pragma unroll
    for (int u = 0; u < UO; u++) {
        int g = g0 + u;
        if (g < L_SAMPLES) {
            float fup = f0_interp(sf0, g);
            float res = (fup >= 20.0f) ? acc[u] : noise[row * L_SAMPLES + g];
            out[row * L_SAMPLES + g] = res;
        }
    }
}

// ---------------------------------------------------------------------------
extern "C" void kernel_launch(void* const* d_in, const int* in_sizes, int n_in,
                              void* d_out, int out_size) {
    const float* f0    = (const float*)d_in[0];
    const float* noise = (const float*)d_in[1];
    const float* kern  = (const float*)d_in[2];
    float* out = (float*)d_out;

    dim3 gchunk((NCHUNK + 255) / 256, N_BATCH);
    k1_up<<<gchunk, 256>>>(f0);

    int smem_bytes = (22512 + L1P + L2P + 8) * 4;
    cudaFuncSetAttribute(k2_mid, cudaFuncAttributeMaxDynamicSharedMemorySize, smem_bytes);
    k2_mid<<<N_BATCH, 1024, smem_bytes>>>();

    k3_impulse<<<gchunk, 256>>>(f0);

    dim3 gconv((L_SAMPLES + OTILE - 1) / OTILE, N_BATCH);
    k4_conv<<<gconv, CTH>>>(f0, noise, kern, out);
}

// round 14
// speedup vs baseline: 1.2194x; 1.2194x over previous
#include <cuda_runtime.h>

#define L_SAMPLES 360000
#define N_BATCH   32
#define T_FRAMES  750
#define KSIZE     1003
#define NCHUNK    22500

#define L1N 1407
#define L1P 1408
#define L2N 88
#define L2P 96
#define L3N 6

#define RCP_SR   (1.0f / 24000.0f)
#define RCP_FS   (1.0f / 480.0f)

__device__ float g_E4[N_BATCH][NCHUNK];
__device__ float g_P [N_BATCH][NCHUNK];
__device__ float g_imp[N_BATCH][L_SAMPLES];

// ---------------------------------------------------------------------------
// Bitwise reference elementwise math (FROZEN — verified)
// ---------------------------------------------------------------------------
__device__ __forceinline__ float f0_interp(const float* __restrict__ f0row, int i) {
    float x = __fmul_rn(__fadd_rn((float)i, 0.5f), RCP_FS);
    x = __fadd_rn(x, -0.5f);
    x = fminf(fmaxf(x, 0.0f), 749.0f);
    float fi0 = floorf(x);
    int i0 = (int)fi0;
    int i1 = i0 + 1; if (i1 > 749) i1 = 749;
    float w = __fadd_rn(x, -fi0);
    float a = __fmul_rn(f0row[i0], __fadd_rn(1.0f, -w));
    float b = __fmul_rn(f0row[i1], w);
    return __fadd_rn(a, b);
}

__device__ __forceinline__ float vval(const float* __restrict__ f0row, int i) {
    return __fmul_rn(-f0_interp(f0row, i), RCP_SR);
}

__device__ __forceinline__ float jmod1(float r) {
    float t = fmodf(r, 1.0f);
    if (t != 0.0f && t < 0.0f) t = __fadd_rn(t, 1.0f);
    return t;
}

__device__ __forceinline__ void seq16(const float* __restrict__ in, float* __restrict__ out) {
    float acc = 0.0f;
#pragma unroll
    for (int i = 0; i < 16; i++) { acc = __fadd_rn(acc, in[i]); out[i] = acc; }
}

// ---------------------------------------------------------------------------
// K1 (FROZEN)
// ---------------------------------------------------------------------------
__global__ void k1_up(const float* __restrict__ f0) {
    __shared__ float sf0[T_FRAMES];
    int row = blockIdx.y;
    for (int j = threadIdx.x; j < T_FRAMES; j += blockDim.x)
        sf0[j] = f0[row * T_FRAMES + j];
    __syncthreads();

    int c = blockIdx.x * blockDim.x + threadIdx.x;
    if (c >= NCHUNK) return;
    int base = c * 16;

    float acc = 0.0f;
#pragma unroll
    for (int j = 0; j < 16; j++) acc = __fadd_rn(acc, vval(sf0, base + j));
    g_E4[row][c] = acc;
}

// ---------------------------------------------------------------------------
// K2 (FROZEN)
// ---------------------------------------------------------------------------
__global__ void k2_mid() {
    extern __shared__ float sm[];
    float* s0 = sm;
    float* s1 = sm + 22512;
    float* s2 = s1 + L1P;
    float* s3 = s2 + L2P;
    int row = blockIdx.x;

    for (int i = threadIdx.x; i < 22512; i += blockDim.x)
        s0[i] = (i < NCHUNK) ? g_E4[row][i] : 0.0f;
    __syncthreads();

    for (int b = threadIdx.x; b < L1N; b += blockDim.x) {
        float w[16];
        seq16(s0 + 16*b, w);
#pragma unroll
        for (int i = 0; i < 16; i++) s0[16*b + i] = w[i];
        s1[b] = w[15];
    }
    if (threadIdx.x == 0) s1[L1N] = 0.0f;
    __syncthreads();

    for (int b = threadIdx.x; b < L2N; b += blockDim.x) {
        float w[16];
        seq16(s1 + 16*b, w);
#pragma unroll
        for (int i = 0; i < 16; i++) s1[16*b + i] = w[i];
        s2[b] = w[15];
    }
    for (int i = L2N + threadIdx.x; i < L2P; i += blockDim.x) s2[i] = 0.0f;
    __syncthreads();

    for (int b = threadIdx.x; b < L3N; b += blockDim.x) {
        float w[16];
        seq16(s2 + 16*b, w);
#pragma unroll
        for (int i = 0; i < 16; i++) s2[16*b + i] = w[i];
        s3[b] = w[15];
    }
    __syncthreads();

    if (threadIdx.x == 0) {
        float acc = 0.0f;
        for (int i = 0; i < L3N; i++) { acc = __fadd_rn(acc, s3[i]); s3[i] = acc; }
    }
    __syncthreads();

    for (int j = threadIdx.x; j < L2N; j += blockDim.x) {
        int b = j >> 4;
        s2[j] = __fadd_rn(s2[j], b ? s3[b-1] : 0.0f);
    }
    __syncthreads();
    for (int j = threadIdx.x; j < L1N; j += blockDim.x) {
        int b = j >> 4;
        s1[j] = __fadd_rn(s1[j], b ? s2[b-1] : 0.0f);
    }
    __syncthreads();
    for (int j = threadIdx.x; j < NCHUNK; j += blockDim.x) {
        int b = j >> 4;
        g_P[row][j] = __fadd_rn(s0[j], b ? s1[b-1] : 0.0f);
    }
}

// ---------------------------------------------------------------------------
// K3 (FROZEN)
// ---------------------------------------------------------------------------
__global__ void k3_impulse(const float* __restrict__ f0) {
    __shared__ float sf0[T_FRAMES];
    int row = blockIdx.y;
    for (int j = threadIdx.x; j < T_FRAMES; j += blockDim.x)
        sf0[j] = f0[row * T_FRAMES + j];
    __syncthreads();

    int c = blockIdx.x * blockDim.x + threadIdx.x;
    if (c >= NCHUNK) return;
    int base = c * 16;

    float e0[16];
#pragma unroll
    for (int j = 0; j < 16; j++) e0[j] = vval(sf0, base + j);
    float h[16];
    seq16(e0, h);

    float P = (c == 0) ? 0.0f : g_P[row][c - 1];

    float pr;
    if (c == 0)      pr = __fadd_rn(g_E4[row][NCHUNK-1], g_P[row][NCHUNK-2]);
    else if (c == 1) pr = __fadd_rn(g_E4[row][0], 0.0f);
    else             pr = __fadd_rn(g_E4[row][c-1], g_P[row][c-2]);
    float prev_saw = jmod1(pr);

#pragma unroll
    for (int j = 0; j < 16; j++) {
        float s = jmod1(__fadd_rn(h[j], P));
        g_imp[row][base + j] = __fadd_rn(s, -prev_saw);
        prev_saw = s;
    }
}

// ---------------------------------------------------------------------------
// K4: FFMA2 FIR with tap-parity lane split. Single window copy (parity-
// deinterleaved float4 planes, read as ulonglong2). Even outputs: aligned
// window pairs x aligned weight pairs (w[2m],w[2m+1]). Odd outputs: aligned
// window pairs x SHIFTED weight pairs (w[2m+1],w[2m+2]) + scalar w[0]*f[u].
// Output u = lane_lo + lane_hi (+ edge).
// ---------------------------------------------------------------------------
#define CTH    256
#define UO     8
#define OTILE  2048
#define NPLANE 384               // ulonglong2 per plane; f2 indices 0..1535
#define NWU    256               // ulonglong2 per weight table (512 float2)

#define FFMA2(acc, a, b) asm("fma.rn.f32x2 %0, %1, %2, %0;" : "+l"(acc) : "l"(a), "l"(b))
#define UNPACK2(lo, hi, p) asm("mov.b64 {%0,%1}, %2;" : "=f"(lo), "=f"(hi) : "l"(p))

__global__ __launch_bounds__(CTH) void k4_conv(const float* __restrict__ f0,
                                               const float* __restrict__ noise,
                                               const float* __restrict__ kern,
                                               float* __restrict__ out) {
    __shared__ ulonglong2 pl0q[NPLANE];    // even float4s of the window
    __shared__ ulonglong2 pl1q[NPLANE];    // odd  float4s
    __shared__ ulonglong2 wAq[NWU];        // (w[2m], w[2m+1]) pairs
    __shared__ ulonglong2 wBq[NWU];        // (w[2m+1], w[2m+2]) pairs
    __shared__ float      sf0[T_FRAMES];

    const int row  = blockIdx.y;
    const int base = blockIdx.x * OTILE;
    const int t    = threadIdx.x;

    // weight tables (w[k]=0 for k>=KSIZE)
    {
        float2* wA2 = (float2*)wAq;
        float2* wB2 = (float2*)wBq;
        for (int m = t; m < 2 * NWU; m += CTH) {
            float w0 = (2*m     < KSIZE) ? kern[2*m]     : 0.0f;
            float w1 = (2*m + 1 < KSIZE) ? kern[2*m + 1] : 0.0f;
            float w2 = (2*m + 2 < KSIZE) ? kern[2*m + 2] : 0.0f;
            wA2[m] = make_float2(w0, w1);
            wB2[m] = make_float2(w1, w2);
        }
    }
    for (int j = t; j < T_FRAMES; j += CTH)
        sf0[j] = f0[row * T_FRAMES + j];

    // window planes (float4 jf covers samples base+4jf..+3; even jf->pl0)
    {
        const float* impRow = g_imp[row];
        float4* p0 = (float4*)pl0q;
        float4* p1 = (float4*)pl1q;
        for (int jf = t; jf < 2 * NPLANE; jf += CTH) {
            int g = base + 4 * jf;
            float4 v;
            if (g + 3 < L_SAMPLES) {
                v = *reinterpret_cast<const float4*>(impRow + g);
            } else {
                v.x = (g + 0 < L_SAMPLES) ? impRow[g + 0] : 0.0f;
                v.y = (g + 1 < L_SAMPLES) ? impRow[g + 1] : 0.0f;
                v.z = (g + 2 < L_SAMPLES) ? impRow[g + 2] : 0.0f;
                v.w = (g + 3 < L_SAMPLES) ? impRow[g + 3] : 0.0f;
            }
            if (jf & 1) p1[jf >> 1] = v;
            else        p0[jf >> 1] = v;
        }
    }
    __syncthreads();

    // accumulators: lanes = (even-tap partial, odd-tap partial) per output
    unsigned long long aE[4] = {0ull, 0ull, 0ull, 0ull};  // outputs 0,2,4,6
    unsigned long long aO[4] = {0ull, 0ull, 0ull, 0ull};  // outputs 1,3,5,7 (tap stream shifted by 1)

    ulonglong2 Q0 = pl0q[t];
    ulonglong2 Q1 = pl1q[t];
    ulonglong2 Q2 = pl0q[t + 1];
    ulonglong2 Q3 = pl1q[t + 1];

    // edge samples for odd outputs' scalar w[0] term: f[g0+1,3,5,7]
    float e1, e3, e5, e7, junk;
    UNPACK2(junk, e1, Q0.x);
    UNPACK2(junk, e3, Q0.y);
    UNPACK2(junk, e5, Q1.x);
    UNPACK2(junk, e7, Q1.y);

#pragma unroll 2
    for (int it = 0; it < 126; ++it) {
        ulonglong2 wa01 = wAq[2*it], wa23 = wAq[2*it + 1];
        ulonglong2 wb01 = wBq[2*it], wb23 = wBq[2*it + 1];
        unsigned long long F[8] = {Q0.x, Q0.y, Q1.x, Q1.y, Q2.x, Q2.y, Q3.x, Q3.y};
        unsigned long long wa[4] = {wa01.x, wa01.y, wa23.x, wa23.y};
        unsigned long long wb[4] = {wb01.x, wb01.y, wb23.x, wb23.y};

#pragma unroll
        for (int m = 0; m < 4; m++) {
#pragma unroll
            for (int u = 0; u < 4; u++) {
                FFMA2(aE[u], F[u + m],     wa[m]);
                FFMA2(aO[u], F[u + 1 + m], wb[m]);
            }
        }

        Q0 = Q2; Q1 = Q3;
        Q2 = pl0q[t + it + 2];
        Q3 = pl1q[t + it + 2];
    }

    // epilogue
    float w0k = kern[0];
    float eo[4] = {e1, e3, e5, e7};
    float acc[UO];
#pragma unroll
    for (int u = 0; u < 4; u++) {
        float lo, hi;
        UNPACK2(lo, hi, aE[u]);
        acc[2*u] = lo + hi;
        UNPACK2(lo, hi, aO[u]);
        acc[2*u + 1] = fmaf(w0k, eo[u], lo + hi);
    }

    int g0 = base + UO * t;
#pragma unroll
    for (int u = 0; u < UO; u++) {
        int g = g0 + u;
        if (g < L_SAMPLES) {
            float fup = f0_interp(sf0, g);
            float res = (fup >= 20.0f) ? acc[u] : noise[row * L_SAMPLES + g];
            out[row * L_SAMPLES + g] = res;
        }
    }
}

// ---------------------------------------------------------------------------
extern "C" void kernel_launch(void* const* d_in, const int* in_sizes, int n_in,
                              void* d_out, int out_size) {
    const float* f0    = (const float*)d_in[0];
    const float* noise = (const float*)d_in[1];
    const float* kern  = (const float*)d_in[2];
    float* out = (float*)d_out;

    dim3 gchunk((NCHUNK + 255) / 256, N_BATCH);
    k1_up<<<gchunk, 256>>>(f0);

    int smem_bytes = (22512 + L1P + L2P + 8) * 4;
    cudaFuncSetAttribute(k2_mid, cudaFuncAttributeMaxDynamicSharedMemorySize, smem_bytes);
    k2_mid<<<N_BATCH, 1024, smem_bytes>>>();

    k3_impulse<<<gchunk, 256>>>(f0);

    dim3 gconv((L_SAMPLES + OTILE - 1) / OTILE, N_BATCH);
    k4_conv<<<gconv, CTH>>>(f0, noise, kern, out);
}

// round 16
// speedup vs baseline: 1.9166x; 1.5717x over previous
#include <cuda_runtime.h>
#include <cuda_bf16.h>
#include <cstdint>

#define L_SAMPLES 360000
#define N_BATCH   32
#define T_FRAMES  750
#define KSIZE     1003
#define NCHUNK    22500

#define L1N 1407
#define L1P 1408
#define L2N 88
#define L2P 96
#define L3N 6

#define RCP_SR   (1.0f / 24000.0f)
#define RCP_FS   (1.0f / 480.0f)

#define NKS    80        // K slices of 16 (K = 1280 >= 1003 + 127)

__device__ float g_E4[N_BATCH][NCHUNK];
__device__ float g_P [N_BATCH][NCHUNK];
__device__ float g_imp[N_BATCH][L_SAMPLES];
// W slices: [ks][hi/lo][r(128)][kk(16)] bf16, slice = 8192B
__device__ __nv_bfloat16 g_Wk[NKS][2][128][16];

// ---------------------------------------------------------------------------
// Bitwise reference elementwise math (FROZEN — verified)
// ---------------------------------------------------------------------------
__device__ __forceinline__ float f0_interp(const float* __restrict__ f0row, int i) {
    float x = __fmul_rn(__fadd_rn((float)i, 0.5f), RCP_FS);
    x = __fadd_rn(x, -0.5f);
    x = fminf(fmaxf(x, 0.0f), 749.0f);
    float fi0 = floorf(x);
    int i0 = (int)fi0;
    int i1 = i0 + 1; if (i1 > 749) i1 = 749;
    float w = __fadd_rn(x, -fi0);
    float a = __fmul_rn(f0row[i0], __fadd_rn(1.0f, -w));
    float b = __fmul_rn(f0row[i1], w);
    return __fadd_rn(a, b);
}
__device__ __forceinline__ float vval(const float* __restrict__ f0row, int i) {
    return __fmul_rn(-f0_interp(f0row, i), RCP_SR);
}
__device__ __forceinline__ float jmod1(float r) {
    float t = fmodf(r, 1.0f);
    if (t != 0.0f && t < 0.0f) t = __fadd_rn(t, 1.0f);
    return t;
}
__device__ __forceinline__ void seq16(const float* __restrict__ in, float* __restrict__ out) {
    float acc = 0.0f;
#pragma unroll
    for (int i = 0; i < 16; i++) { acc = __fadd_rn(acc, in[i]); out[i] = acc; }
}

// --------------------------- K1 (FROZEN) -----------------------------------
__global__ void k1_up(const float* __restrict__ f0) {
    __shared__ float sf0[T_FRAMES];
    int row = blockIdx.y;
    for (int j = threadIdx.x; j < T_FRAMES; j += blockDim.x)
        sf0[j] = f0[row * T_FRAMES + j];
    __syncthreads();
    int c = blockIdx.x * blockDim.x + threadIdx.x;
    if (c >= NCHUNK) return;
    int base = c * 16;
    float acc = 0.0f;
#pragma unroll
    for (int j = 0; j < 16; j++) acc = __fadd_rn(acc, vval(sf0, base + j));
    g_E4[row][c] = acc;
}

// --------------------------- K2 (FROZEN) -----------------------------------
__global__ void k2_mid() {
    extern __shared__ float sm[];
    float* s0 = sm;
    float* s1 = sm + 22512;
    float* s2 = s1 + L1P;
    float* s3 = s2 + L2P;
    int row = blockIdx.x;
    for (int i = threadIdx.x; i < 22512; i += blockDim.x)
        s0[i] = (i < NCHUNK) ? g_E4[row][i] : 0.0f;
    __syncthreads();
    for (int b = threadIdx.x; b < L1N; b += blockDim.x) {
        float w[16]; seq16(s0 + 16*b, w);
#pragma unroll
        for (int i = 0; i < 16; i++) s0[16*b + i] = w[i];
        s1[b] = w[15];
    }
    if (threadIdx.x == 0) s1[L1N] = 0.0f;
    __syncthreads();
    for (int b = threadIdx.x; b < L2N; b += blockDim.x) {
        float w[16]; seq16(s1 + 16*b, w);
#pragma unroll
        for (int i = 0; i < 16; i++) s1[16*b + i] = w[i];
        s2[b] = w[15];
    }
    for (int i = L2N + threadIdx.x; i < L2P; i += blockDim.x) s2[i] = 0.0f;
    __syncthreads();
    for (int b = threadIdx.x; b < L3N; b += blockDim.x) {
        float w[16]; seq16(s2 + 16*b, w);
#pragma unroll
        for (int i = 0; i < 16; i++) s2[16*b + i] = w[i];
        s3[b] = w[15];
    }
    __syncthreads();
    if (threadIdx.x == 0) {
        float acc = 0.0f;
        for (int i = 0; i < L3N; i++) { acc = __fadd_rn(acc, s3[i]); s3[i] = acc; }
    }
    __syncthreads();
    for (int j = threadIdx.x; j < L2N; j += blockDim.x) {
        int b = j >> 4;
        s2[j] = __fadd_rn(s2[j], b ? s3[b-1] : 0.0f);
    }
    __syncthreads();
    for (int j = threadIdx.x; j < L1N; j += blockDim.x) {
        int b = j >> 4;
        s1[j] = __fadd_rn(s1[j], b ? s2[b-1] : 0.0f);
    }
    __syncthreads();
    for (int j = threadIdx.x; j < NCHUNK; j += blockDim.x) {
        int b = j >> 4;
        g_P[row][j] = __fadd_rn(s0[j], b ? s1[b-1] : 0.0f);
    }
}

// --------------------------- K3 (FROZEN) -----------------------------------
__global__ void k3_impulse(const float* __restrict__ f0) {
    __shared__ float sf0[T_FRAMES];
    int row = blockIdx.y;
    for (int j = threadIdx.x; j < T_FRAMES; j += blockDim.x)
        sf0[j] = f0[row * T_FRAMES + j];
    __syncthreads();
    int c = blockIdx.x * blockDim.x + threadIdx.x;
    if (c >= NCHUNK) return;
    int base = c * 16;
    float e0[16];
#pragma unroll
    for (int j = 0; j < 16; j++) e0[j] = vval(sf0, base + j);
    float h[16]; seq16(e0, h);
    float P = (c == 0) ? 0.0f : g_P[row][c - 1];
    float pr;
    if (c == 0)      pr = __fadd_rn(g_E4[row][NCHUNK-1], g_P[row][NCHUNK-2]);
    else if (c == 1) pr = __fadd_rn(g_E4[row][0], 0.0f);
    else             pr = __fadd_rn(g_E4[row][c-1], g_P[row][c-2]);
    float prev_saw = jmod1(pr);
#pragma unroll
    for (int j = 0; j < 16; j++) {
        float s = jmod1(__fadd_rn(h[j], P));
        g_imp[row][base + j] = __fadd_rn(s, -prev_saw);
        prev_saw = s;
    }
}

// ---------------------------------------------------------------------------
// K_W: W[r, j] = w[j - r], sliced by 16 along j; bf16 hi/lo split.
// ---------------------------------------------------------------------------
__global__ void k_w(const float* __restrict__ kern) {
    int ks = blockIdx.x;
    for (int idx = threadIdx.x; idx < 128 * 16; idx += blockDim.x) {
        int r = idx >> 4, kk = idx & 15;
        int j = 16 * ks + kk - r;
        float v = (j >= 0 && j < KSIZE) ? kern[j] : 0.0f;
        __nv_bfloat16 hi = __float2bfloat16(v);
        __nv_bfloat16 lo = __float2bfloat16(v - __bfloat162float(hi));
        g_Wk[ks][0][r][kk] = hi;
        g_Wk[ks][1][r][kk] = lo;
    }
}

// ---------------------------------------------------------------------------
// K4: warp-MMA (m16n8k16 bf16) Toeplitz GEMM.
// Per CTA: one audio row, 128 block-columns (16384 outputs).
// D[r, n] = sum_j W[r, j] * imp[S0 + 128 n + j],  r,n in 0..127, j < 1280.
// 3 bf16 products per k-slice: Ah*Bh + Ah*Bl + Al*Bh.
// Warp tile 32(M) x 64(N): 8 warps = 4 rowgrps x 2 colgrps.
// ---------------------------------------------------------------------------
#define K4T     256
#define SW_OFF  0                        // W slice: [2][128][24] bf16 (48B rows)
#define SW_BYTES (2 * 128 * 48)          // 12288
#define XH_OFF  12288                    // bf16 hi window, swizzled
#define XL_OFF  47488                    // bf16 lo window
#define XBYTES  35200                    // 17536*2 + swizzle pad
#define F0_OFF  82688
#define K4_SMEM 85760

#define SWZ(a) ((a) ^ ((((a) >> 8) & 7) << 4))

__device__ __forceinline__ void mma_bf16(float* d, const uint32_t* a, uint32_t b0, uint32_t b1) {
    asm volatile("mma.sync.aligned.m16n8k16.row.col.f32.bf16.bf16.f32 "
                 "{%0,%1,%2,%3}, {%4,%5,%6,%7}, {%8,%9}, {%0,%1,%2,%3};"
                 : "+f"(d[0]), "+f"(d[1]), "+f"(d[2]), "+f"(d[3])
                 : "r"(a[0]), "r"(a[1]), "r"(a[2]), "r"(a[3]), "r"(b0), "r"(b1));
}

__global__ void __launch_bounds__(K4T, 2) k4_mma(const float* __restrict__ f0,
                                                 const float* __restrict__ noise,
                                                 float* __restrict__ out) {
    extern __shared__ char smc[];
    const int row = blockIdx.y;
    const int S0  = blockIdx.x * 16384;
    const int tid = threadIdx.x;
    const int lane = tid & 31, wid = tid >> 5;
    const int quad = lane >> 2, tq = lane & 3;
    const int rowgrp = wid & 3, colgrp = wid >> 2;

    float* sf0 = (float*)(smc + F0_OFF);
    for (int j = tid; j < T_FRAMES; j += K4T) sf0[j] = f0[row * T_FRAMES + j];

    // ---- stage imp window: fp32 -> bf16 hi/lo pairs, XOR-swizzled ----
    {
        const float* impRow = g_imp[row];
#pragma unroll 4
        for (int p = tid; p < 8768; p += K4T) {       // pair p = floats 2p, 2p+1
            int g = S0 + 2 * p;
            float v0 = (g     < L_SAMPLES) ? impRow[g]     : 0.0f;
            float v1 = (g + 1 < L_SAMPLES) ? impRow[g + 1] : 0.0f;
            __nv_bfloat16 h0 = __float2bfloat16(v0), h1 = __float2bfloat16(v1);
            __nv_bfloat16 l0 = __float2bfloat16(v0 - __bfloat162float(h0));
            __nv_bfloat16 l1 = __float2bfloat16(v1 - __bfloat162float(h1));
            __nv_bfloat162 hp(h0, h1), lp(l0, l1);
            int a = 4 * p;
            *(uint32_t*)(smc + XH_OFF + SWZ(a)) = *(uint32_t*)&hp;
            *(uint32_t*)(smc + XL_OFF + SWZ(a)) = *(uint32_t*)&lp;
        }
    }

    // ---- stage W slice 0 ----
    const uint4* gW4 = (const uint4*)g_Wk;
    {
        uint4 v0 = gW4[2 * tid], v1 = gW4[2 * tid + 1];
        int c0 = 2 * tid, c1 = 2 * tid + 1;
        *(uint4*)(smc + SW_OFF + (c0 >> 8) * 6144 + ((c0 >> 1) & 127) * 48 + (c0 & 1) * 16) = v0;
        *(uint4*)(smc + SW_OFF + (c1 >> 8) * 6144 + ((c1 >> 1) & 127) * 48 + (c1 & 1) * 16) = v1;
    }
    __syncthreads();

    float D[2][8][4];
#pragma unroll
    for (int ch = 0; ch < 2; ch++)
#pragma unroll
        for (int s = 0; s < 8; s++)
#pragma unroll
            for (int i = 0; i < 4; i++) D[ch][s][i] = 0.0f;

    for (int ks = 0; ks < NKS; ks++) {
        uint4 pf0, pf1;
        if (ks + 1 < NKS) {
            pf0 = gW4[(ks + 1) * 512 + 2 * tid];
            pf1 = gW4[(ks + 1) * 512 + 2 * tid + 1];
        }

        // A fragments (hi and lo) for 2 row-chunks
        uint32_t ah[2][4], al[2][4];
#pragma unroll
        for (int ch = 0; ch < 2; ch++) {
            int rr = 32 * rowgrp + 16 * ch + quad;
            const char* pA = smc + SW_OFF;
            ah[ch][0] = *(const uint32_t*)(pA + rr * 48 + 4 * tq);
            ah[ch][1] = *(const uint32_t*)(pA + (rr + 8) * 48 + 4 * tq);
            ah[ch][2] = *(const uint32_t*)(pA + rr * 48 + 4 * tq + 16);
            ah[ch][3] = *(const uint32_t*)(pA + (rr + 8) * 48 + 4 * tq + 16);
            al[ch][0] = *(const uint32_t*)(pA + 6144 + rr * 48 + 4 * tq);
            al[ch][1] = *(const uint32_t*)(pA + 6144 + (rr + 8) * 48 + 4 * tq);
            al[ch][2] = *(const uint32_t*)(pA + 6144 + rr * 48 + 4 * tq + 16);
            al[ch][3] = *(const uint32_t*)(pA + 6144 + (rr + 8) * 48 + 4 * tq + 16);
        }

        int kb = 32 * ks + 4 * tq;   // byte offset of 2*k for b0
#pragma unroll
        for (int sub = 0; sub < 8; sub++) {
            int n = 8 * (8 * colgrp + sub) + quad;
            int a0 = 256 * n + kb;
            uint32_t bh0 = *(const uint32_t*)(smc + XH_OFF + SWZ(a0));
            uint32_t bh1 = *(const uint32_t*)(smc + XH_OFF + SWZ(a0 + 16));
            uint32_t bl0 = *(const uint32_t*)(smc + XL_OFF + SWZ(a0));
            uint32_t bl1 = *(const uint32_t*)(smc + XL_OFF + SWZ(a0 + 16));
#pragma unroll
            for (int ch = 0; ch < 2; ch++) {
                mma_bf16(D[ch][sub], ah[ch], bh0, bh1);
                mma_bf16(D[ch][sub], ah[ch], bl0, bl1);
                mma_bf16(D[ch][sub], al[ch], bh0, bh1);
            }
        }

        __syncthreads();
        if (ks + 1 < NKS) {
            int c0 = 2 * tid, c1 = 2 * tid + 1;
            *(uint4*)(smc + SW_OFF + (c0 >> 8) * 6144 + ((c0 >> 1) & 127) * 48 + (c0 & 1) * 16) = pf0;
            *(uint4*)(smc + SW_OFF + (c1 >> 8) * 6144 + ((c1 >> 1) & 127) * 48 + (c1 & 1) * 16) = pf1;
        }
        __syncthreads();
    }

    // ---- epilogue: D[r, n] -> out[S0 + 128 n + r] with voiced select ----
    const float* nsRow = noise + (size_t)row * L_SAMPLES;
    float* outRow = out + (size_t)row * L_SAMPLES;
#pragma unroll
    for (int ch = 0; ch < 2; ch++) {
#pragma unroll
        for (int sub = 0; sub < 8; sub++) {
            int n_b = 8 * (8 * colgrp + sub) + 2 * tq;
            int r_b = 32 * rowgrp + 16 * ch + quad;
#pragma unroll
            for (int i = 0; i < 4; i++) {
                int g = S0 + 128 * (n_b + (i & 1)) + r_b + (i >> 1) * 8;
                if (g < L_SAMPLES) {
                    float fup = f0_interp(sf0, g);
                    float res = (fup >= 20.0f) ? D[ch][sub][i] : nsRow[g];
                    outRow[g] = res;
                }
            }
        }
    }
}

// ---------------------------------------------------------------------------
extern "C" void kernel_launch(void* const* d_in, const int* in_sizes, int n_in,
                              void* d_out, int out_size) {
    const float* f0    = (const float*)d_in[0];
    const float* noise = (const float*)d_in[1];
    const float* kern  = (const float*)d_in[2];
    float* out = (float*)d_out;

    k_w<<<NKS, 256>>>(kern);

    dim3 gchunk((NCHUNK + 255) / 256, N_BATCH);
    k1_up<<<gchunk, 256>>>(f0);

    int smem_bytes = (22512 + L1P + L2P + 8) * 4;
    cudaFuncSetAttribute(k2_mid, cudaFuncAttributeMaxDynamicSharedMemorySize, smem_bytes);
    k2_mid<<<N_BATCH, 1024, smem_bytes>>>();

    k3_impulse<<<gchunk, 256>>>(f0);

    cudaFuncSetAttribute(k4_mma, cudaFuncAttributeMaxDynamicSharedMemorySize, K4_SMEM);
    dim3 gmma(22, N_BATCH);
    k4_mma<<<gmma, K4T, K4_SMEM>>>(f0, noise, out);
}

// round 17
// speedup vs baseline: 2.0377x; 1.0632x over previous
#include <cuda_runtime.h>
#include <cuda_bf16.h>
#include <cstdint>

#define L_SAMPLES 360000
#define N_BATCH   32
#define T_FRAMES  750
#define KSIZE     1003
#define NCHUNK    22500

#define L1N 1407
#define L1P 1408
#define L2N 88
#define L2P 96
#define L3N 6

#define RCP_SR   (1.0f / 24000.0f)
#define RCP_FS   (1.0f / 480.0f)

#define NKS    80        // K slices of 16 (K = 1280 >= 1003 + 127)

__device__ float g_E4[N_BATCH][NCHUNK];
__device__ float g_P [N_BATCH][NCHUNK];
__device__ float g_imp[N_BATCH][L_SAMPLES];
__device__ float g_leaf[N_BATCH][L_SAMPLES];          // leaf values from k1
__device__ unsigned char g_vc[N_BATCH][L_SAMPLES];    // voiced mask from k1
__device__ __nv_bfloat16 g_Wk[NKS][2][128][16];

// ---------------------------------------------------------------------------
// Bitwise reference elementwise math (FROZEN — verified)
// ---------------------------------------------------------------------------
__device__ __forceinline__ float f0_interp(const float* __restrict__ f0row, int i) {
    float x = __fmul_rn(__fadd_rn((float)i, 0.5f), RCP_FS);
    x = __fadd_rn(x, -0.5f);
    x = fminf(fmaxf(x, 0.0f), 749.0f);
    float fi0 = floorf(x);
    int i0 = (int)fi0;
    int i1 = i0 + 1; if (i1 > 749) i1 = 749;
    float w = __fadd_rn(x, -fi0);
    float a = __fmul_rn(f0row[i0], __fadd_rn(1.0f, -w));
    float b = __fmul_rn(f0row[i1], w);
    return __fadd_rn(a, b);
}
__device__ __forceinline__ float jmod1(float r) {
    float t = fmodf(r, 1.0f);
    if (t != 0.0f && t < 0.0f) t = __fadd_rn(t, 1.0f);
    return t;
}
__device__ __forceinline__ void seq16(const float* __restrict__ in, float* __restrict__ out) {
    float acc = 0.0f;
#pragma unroll
    for (int i = 0; i < 16; i++) { acc = __fadd_rn(acc, in[i]); out[i] = acc; }
}

// ---------------------------------------------------------------------------
// K1: leaves (stored), tile sums, voiced mask.
// ---------------------------------------------------------------------------
__global__ void k1_up(const float* __restrict__ f0) {
    __shared__ float sf0[T_FRAMES];
    int row = blockIdx.y;
    for (int j = threadIdx.x; j < T_FRAMES; j += blockDim.x)
        sf0[j] = f0[row * T_FRAMES + j];
    __syncthreads();
    int c = blockIdx.x * blockDim.x + threadIdx.x;
    if (c >= NCHUNK) return;
    int base = c * 16;

    float e0[16];
    unsigned char m[16];
#pragma unroll
    for (int j = 0; j < 16; j++) {
        float fup = f0_interp(sf0, base + j);
        e0[j] = __fmul_rn(-fup, RCP_SR);
        m[j] = (fup >= 20.0f) ? 1 : 0;
    }
    float acc = 0.0f;
#pragma unroll
    for (int j = 0; j < 16; j++) acc = __fadd_rn(acc, e0[j]);
    g_E4[row][c] = acc;

    float4* lf = (float4*)(&g_leaf[row][base]);
#pragma unroll
    for (int q = 0; q < 4; q++)
        lf[q] = make_float4(e0[4*q], e0[4*q+1], e0[4*q+2], e0[4*q+3]);
    *(uint4*)(&g_vc[row][base]) = *(uint4*)m;
}

// --------------------------- K2 (FROZEN) -----------------------------------
__global__ void k2_mid() {
    extern __shared__ float sm[];
    float* s0 = sm;
    float* s1 = sm + 22512;
    float* s2 = s1 + L1P;
    float* s3 = s2 + L2P;
    int row = blockIdx.x;
    for (int i = threadIdx.x; i < 22512; i += blockDim.x)
        s0[i] = (i < NCHUNK) ? g_E4[row][i] : 0.0f;
    __syncthreads();
    for (int b = threadIdx.x; b < L1N; b += blockDim.x) {
        float w[16]; seq16(s0 + 16*b, w);
#pragma unroll
        for (int i = 0; i < 16; i++) s0[16*b + i] = w[i];
        s1[b] = w[15];
    }
    if (threadIdx.x == 0) s1[L1N] = 0.0f;
    __syncthreads();
    for (int b = threadIdx.x; b < L2N; b += blockDim.x) {
        float w[16]; seq16(s1 + 16*b, w);
#pragma unroll
        for (int i = 0; i < 16; i++) s1[16*b + i] = w[i];
        s2[b] = w[15];
    }
    for (int i = L2N + threadIdx.x; i < L2P; i += blockDim.x) s2[i] = 0.0f;
    __syncthreads();
    for (int b = threadIdx.x; b < L3N; b += blockDim.x) {
        float w[16]; seq16(s2 + 16*b, w);
#pragma unroll
        for (int i = 0; i < 16; i++) s2[16*b + i] = w[i];
        s3[b] = w[15];
    }
    __syncthreads();
    if (threadIdx.x == 0) {
        float acc = 0.0f;
        for (int i = 0; i < L3N; i++) { acc = __fadd_rn(acc, s3[i]); s3[i] = acc; }
    }
    __syncthreads();
    for (int j = threadIdx.x; j < L2N; j += blockDim.x) {
        int b = j >> 4;
        s2[j] = __fadd_rn(s2[j], b ? s3[b-1] : 0.0f);
    }
    __syncthreads();
    for (int j = threadIdx.x; j < L1N; j += blockDim.x) {
        int b = j >> 4;
        s1[j] = __fadd_rn(s1[j], b ? s2[b-1] : 0.0f);
    }
    __syncthreads();
    for (int j = threadIdx.x; j < NCHUNK; j += blockDim.x) {
        int b = j >> 4;
        g_P[row][j] = __fadd_rn(s0[j], b ? s1[b-1] : 0.0f);
    }
}

// ---------------------------------------------------------------------------
// K3: read stored leaves, in-tile scan + prefix -> impulse.
// ---------------------------------------------------------------------------
__global__ void k3_impulse() {
    int row = blockIdx.y;
    int c = blockIdx.x * blockDim.x + threadIdx.x;
    if (c >= NCHUNK) return;
    int base = c * 16;

    float e0[16];
    const float4* lf = (const float4*)(&g_leaf[row][base]);
#pragma unroll
    for (int q = 0; q < 4; q++) {
        float4 v = lf[q];
        e0[4*q] = v.x; e0[4*q+1] = v.y; e0[4*q+2] = v.z; e0[4*q+3] = v.w;
    }
    float h[16]; seq16(e0, h);

    float P = (c == 0) ? 0.0f : g_P[row][c - 1];
    float pr;
    if (c == 0)      pr = __fadd_rn(g_E4[row][NCHUNK-1], g_P[row][NCHUNK-2]);
    else if (c == 1) pr = __fadd_rn(g_E4[row][0], 0.0f);
    else             pr = __fadd_rn(g_E4[row][c-1], g_P[row][c-2]);
    float prev_saw = jmod1(pr);

    float o[16];
#pragma unroll
    for (int j = 0; j < 16; j++) {
        float s = jmod1(__fadd_rn(h[j], P));
        o[j] = __fadd_rn(s, -prev_saw);
        prev_saw = s;
    }
    float4* ov = (float4*)(&g_imp[row][base]);
#pragma unroll
    for (int q = 0; q < 4; q++)
        ov[q] = make_float4(o[4*q], o[4*q+1], o[4*q+2], o[4*q+3]);
}

// ---------------------------------------------------------------------------
// K_W: W[r, j] = w[j - r], sliced by 16 along j; bf16 hi/lo split.
// ---------------------------------------------------------------------------
__global__ void k_w(const float* __restrict__ kern) {
    int ks = blockIdx.x;
    for (int idx = threadIdx.x; idx < 128 * 16; idx += blockDim.x) {
        int r = idx >> 4, kk = idx & 15;
        int j = 16 * ks + kk - r;
        float v = (j >= 0 && j < KSIZE) ? kern[j] : 0.0f;
        __nv_bfloat16 hi = __float2bfloat16(v);
        __nv_bfloat16 lo = __float2bfloat16(v - __bfloat162float(hi));
        g_Wk[ks][0][r][kk] = hi;
        g_Wk[ks][1][r][kk] = lo;
    }
}

// ---------------------------------------------------------------------------
// K4: warp-MMA (m16n8k16 bf16) Toeplitz GEMM (unchanged core).
// Epilogue uses the precomputed voiced mask (no interp recompute).
// ---------------------------------------------------------------------------
#define K4T     256
#define SW_OFF  0
#define XH_OFF  12288
#define XL_OFF  47488
#define K4_SMEM 82688

#define SWZ(a) ((a) ^ ((((a) >> 8) & 7) << 4))

__device__ __forceinline__ void mma_bf16(float* d, const uint32_t* a, uint32_t b0, uint32_t b1) {
    asm volatile("mma.sync.aligned.m16n8k16.row.col.f32.bf16.bf16.f32 "
                 "{%0,%1,%2,%3}, {%4,%5,%6,%7}, {%8,%9}, {%0,%1,%2,%3};"
                 : "+f"(d[0]), "+f"(d[1]), "+f"(d[2]), "+f"(d[3])
                 : "r"(a[0]), "r"(a[1]), "r"(a[2]), "r"(a[3]), "r"(b0), "r"(b1));
}

__global__ void __launch_bounds__(K4T, 2) k4_mma(const float* __restrict__ noise,
                                                 float* __restrict__ out) {
    extern __shared__ char smc[];
    const int row = blockIdx.y;
    const int S0  = blockIdx.x * 16384;
    const int tid = threadIdx.x;
    const int lane = tid & 31, wid = tid >> 5;
    const int quad = lane >> 2, tq = lane & 3;
    const int rowgrp = wid & 3, colgrp = wid >> 2;

    // ---- stage imp window: fp32 -> bf16 hi/lo pairs, XOR-swizzled ----
    {
        const float* impRow = g_imp[row];
#pragma unroll 4
        for (int p = tid; p < 8768; p += K4T) {
            int g = S0 + 2 * p;
            float v0 = (g     < L_SAMPLES) ? impRow[g]     : 0.0f;
            float v1 = (g + 1 < L_SAMPLES) ? impRow[g + 1] : 0.0f;
            __nv_bfloat16 h0 = __float2bfloat16(v0), h1 = __float2bfloat16(v1);
            __nv_bfloat16 l0 = __float2bfloat16(v0 - __bfloat162float(h0));
            __nv_bfloat16 l1 = __float2bfloat16(v1 - __bfloat162float(h1));
            __nv_bfloat162 hp(h0, h1), lp(l0, l1);
            int a = 4 * p;
            *(uint32_t*)(smc + XH_OFF + SWZ(a)) = *(uint32_t*)&hp;
            *(uint32_t*)(smc + XL_OFF + SWZ(a)) = *(uint32_t*)&lp;
        }
    }

    // ---- stage W slice 0 ----
    const uint4* gW4 = (const uint4*)g_Wk;
    {
        uint4 v0 = gW4[2 * tid], v1 = gW4[2 * tid + 1];
        int c0 = 2 * tid, c1 = 2 * tid + 1;
        *(uint4*)(smc + SW_OFF + (c0 >> 8) * 6144 + ((c0 >> 1) & 127) * 48 + (c0 & 1) * 16) = v0;
        *(uint4*)(smc + SW_OFF + (c1 >> 8) * 6144 + ((c1 >> 1) & 127) * 48 + (c1 & 1) * 16) = v1;
    }
    __syncthreads();

    float D[2][8][4];
#pragma unroll
    for (int ch = 0; ch < 2; ch++)
#pragma unroll
        for (int s = 0; s < 8; s++)
#pragma unroll
            for (int i = 0; i < 4; i++) D[ch][s][i] = 0.0f;

    for (int ks = 0; ks < NKS; ks++) {
        uint4 pf0, pf1;
        if (ks + 1 < NKS) {
            pf0 = gW4[(ks + 1) * 512 + 2 * tid];
            pf1 = gW4[(ks + 1) * 512 + 2 * tid + 1];
        }

        uint32_t ah[2][4], al[2][4];
#pragma unroll
        for (int ch = 0; ch < 2; ch++) {
            int rr = 32 * rowgrp + 16 * ch + quad;
            const char* pA = smc + SW_OFF;
            ah[ch][0] = *(const uint32_t*)(pA + rr * 48 + 4 * tq);
            ah[ch][1] = *(const uint32_t*)(pA + (rr + 8) * 48 + 4 * tq);
            ah[ch][2] = *(const uint32_t*)(pA + rr * 48 + 4 * tq + 16);
            ah[ch][3] = *(const uint32_t*)(pA + (rr + 8) * 48 + 4 * tq + 16);
            al[ch][0] = *(const uint32_t*)(pA + 6144 + rr * 48 + 4 * tq);
            al[ch][1] = *(const uint32_t*)(pA + 6144 + (rr + 8) * 48 + 4 * tq);
            al[ch][2] = *(const uint32_t*)(pA + 6144 + rr * 48 + 4 * tq + 16);
            al[ch][3] = *(const uint32_t*)(pA + 6144 + (rr + 8) * 48 + 4 * tq + 16);
        }

        int kb = 32 * ks + 4 * tq;
#pragma unroll
        for (int sub = 0; sub < 8; sub++) {
            int n = 8 * (8 * colgrp + sub) + quad;
            int a0 = 256 * n + kb;
            uint32_t bh0 = *(const uint32_t*)(smc + XH_OFF + SWZ(a0));
            uint32_t bh1 = *(const uint32_t*)(smc + XH_OFF + SWZ(a0 + 16));
            uint32_t bl0 = *(const uint32_t*)(smc + XL_OFF + SWZ(a0));
            uint32_t bl1 = *(const uint32_t*)(smc + XL_OFF + SWZ(a0 + 16));
#pragma unroll
            for (int ch = 0; ch < 2; ch++) {
                mma_bf16(D[ch][sub], ah[ch], bh0, bh1);
                mma_bf16(D[ch][sub], ah[ch], bl0, bl1);
                mma_bf16(D[ch][sub], al[ch], bh0, bh1);
            }
        }

        __syncthreads();
        if (ks + 1 < NKS) {
            int c0 = 2 * tid, c1 = 2 * tid + 1;
            *(uint4*)(smc + SW_OFF + (c0 >> 8) * 6144 + ((c0 >> 1) & 127) * 48 + (c0 & 1) * 16) = pf0;
            *(uint4*)(smc + SW_OFF + (c1 >> 8) * 6144 + ((c1 >> 1) & 127) * 48 + (c1 & 1) * 16) = pf1;
        }
        __syncthreads();
    }

    // ---- epilogue: voiced mask select ----
    const float* nsRow = noise + (size_t)row * L_SAMPLES;
    const unsigned char* vcRow = g_vc[row];
    float* outRow = out + (size_t)row * L_SAMPLES;
#pragma unroll
    for (int ch = 0; ch < 2; ch++) {
#pragma unroll
        for (int sub = 0; sub < 8; sub++) {
            int n_b = 8 * (8 * colgrp + sub) + 2 * tq;
            int r_b = 32 * rowgrp + 16 * ch + quad;
#pragma unroll
            for (int i = 0; i < 4; i++) {
                int g = S0 + 128 * (n_b + (i & 1)) + r_b + (i >> 1) * 8;
                if (g < L_SAMPLES) {
                    float res = vcRow[g] ? D[ch][sub][i] : nsRow[g];
                    outRow[g] = res;
                }
            }
        }
    }
}

// ---------------------------------------------------------------------------
extern "C" void kernel_launch(void* const* d_in, const int* in_sizes, int n_in,
                              void* d_out, int out_size) {
    const float* f0    = (const float*)d_in[0];
    const float* noise = (const float*)d_in[1];
    const float* kern  = (const float*)d_in[2];
    float* out = (float*)d_out;

    k_w<<<NKS, 256>>>(kern);

    dim3 gchunk((NCHUNK + 255) / 256, N_BATCH);
    k1_up<<<gchunk, 256>>>(f0);

    int smem_bytes = (22512 + L1P + L2P + 8) * 4;
    cudaFuncSetAttribute(k2_mid, cudaFuncAttributeMaxDynamicSharedMemorySize, smem_bytes);
    k2_mid<<<N_BATCH, 1024, smem_bytes>>>();

    k3_impulse<<<gchunk, 256>>>();

    cudaFuncSetAttribute(k4_mma, cudaFuncAttributeMaxDynamicSharedMemorySize, K4_SMEM);
    dim3 gmma(22, N_BATCH);
    k4_mma<<<gmma, K4T, K4_SMEM>>>(noise, out);
}